// round 6
// baseline (speedup 1.0000x reference)
#include <cuda_runtime.h>

typedef unsigned long long u64t;

#define BB 8
#define TT 100
#define UU 64
#define ZZ 256   // 4U
#define PP 1000
#define NK 50
#define NKP 56   // padded row: [0..24]=k0..24, [25..27]=0, [28..52]=k25..49, [53..55]=0
#define BT (BB*TT) // 800

// Scratch (__device__ globals — no allocation)
__device__ __align__(16) float d_xk[BT*ZZ];        // xt @ lstm_kernel + bias
__device__ __align__(16) float d_g[BB*TT*NKP];     // ht @ W1[0:64], padded layout
__device__ __align__(16) float d_XW[1024*NKP];     // X @ W1[64:192] + b1, padded layout

// ---- packed f32x2 helpers (Blackwell) --------------------------------------
__device__ __forceinline__ u64t f2pk(float lo, float hi) {
    u64t r; asm("mov.b64 %0,{%1,%2};" : "=l"(r) : "f"(lo), "f"(hi)); return r;
}
__device__ __forceinline__ u64t ffma2(u64t a, u64t b, u64t c) {
    u64t d; asm("fma.rn.f32x2 %0,%1,%2,%3;" : "=l"(d) : "l"(a), "l"(b), "l"(c)); return d;
}
__device__ __forceinline__ u64t fadd2(u64t a, u64t b) {
    u64t d; asm("add.rn.f32x2 %0,%1,%2;" : "=l"(d) : "l"(a), "l"(b)); return d;
}
__device__ __forceinline__ float2 f2up(u64t v) {
    float2 r; asm("mov.b64 {%0,%1},%2;" : "=f"(r.x), "=f"(r.y) : "l"(v)); return r;
}

__device__ __forceinline__ float sigf(float x) {
    return __fdividef(1.f, 1.f + __expf(-x));
}
__device__ __forceinline__ float tanhfast(float x) {
    return 1.f - __fdividef(2.f, __expf(2.f*x) + 1.f);
}

// padded position for logical k
__device__ __forceinline__ int padpos(int k) { return (k < 25) ? k : k + 3; }

// ---------------------------------------------------------------------------
// k_pre: blocks 0..103   -> xk GEMM (64x32 tiles, M=800, N=256, K=256)
//        blocks 104..228 -> XW[p,:] = X[p,:] @ W1b + b1   (8 p per block)
// ---------------------------------------------------------------------------
__global__ void __launch_bounds__(256) k_pre(
    const int* __restrict__ pro_id, const int* __restrict__ label,
    const float* __restrict__ X, const float* __restrict__ onehot,
    const float* __restrict__ Kmat, const float* __restrict__ bias,
    const float* __restrict__ W1, const float* __restrict__ b1) {
    __shared__ union {
        struct { float A[32][64]; float B2[32][64]; } g;      // 8KB + 8KB
        struct { float W[128*52]; float Xr[8][128]; } w;      // 26.6KB + 4KB
    } sh;
    int tid = threadIdx.x;
    int bx = blockIdx.x;

    if (bx < 104) {
        // ---- xk GEMM ----
        int mblk = bx % 13, nblk = bx / 13;
        int rowBase = mblk * 64;
        int n0 = nblk * 32;
        int ty = tid >> 4, tx = tid & 15;

        // hoisted A-staging state (two sub-tiles per thread)
        int m0 = tid >> 3;            // 0..31
        int kq = (tid & 7) * 4;       // 0..28
        int row0 = rowBase + m0, row1 = rowBase + m0 + 32;
        bool v0 = row0 < BT, v1 = row1 < BT;
        const float* xp0 = 0; const float* op0 = 0;
        const float* xp1 = 0; const float* op1 = 0;
        if (v0) { xp0 = X + pro_id[row0]*128; op0 = onehot + label[row0]*ZZ; }
        if (v1) { xp1 = X + pro_id[row1]*128; op1 = onehot + label[row1]*ZZ; }

        u64t acc2[2][2] = {{0ull,0ull},{0ull,0ull}};

        for (int k0 = 0; k0 < 256; k0 += 32) {
            int i0 = k0 + kq;
            {   // A sub-tile 0
                float4 v = make_float4(0.f,0.f,0.f,0.f);
                if (v0) {
                    float4 xv = *(const float4*)&xp0[i0 & 127];
                    float4 ov = *(const float4*)&op0[i0];
                    v = make_float4(xv.x*ov.x, xv.y*ov.y, xv.z*ov.z, xv.w*ov.w);
                }
                sh.g.A[kq+0][m0] = v.x; sh.g.A[kq+1][m0] = v.y;
                sh.g.A[kq+2][m0] = v.z; sh.g.A[kq+3][m0] = v.w;
            }
            {   // A sub-tile 1
                float4 v = make_float4(0.f,0.f,0.f,0.f);
                if (v1) {
                    float4 xv = *(const float4*)&xp1[i0 & 127];
                    float4 ov = *(const float4*)&op1[i0];
                    v = make_float4(xv.x*ov.x, xv.y*ov.y, xv.z*ov.z, xv.w*ov.w);
                }
                sh.g.A[kq+0][m0+32] = v.x; sh.g.A[kq+1][m0+32] = v.y;
                sh.g.A[kq+2][m0+32] = v.z; sh.g.A[kq+3][m0+32] = v.w;
            }
            {   // B tile, duplicated pairs: B2[kk][2c]=B2[kk][2c+1]=B[kk][c]
                int kk = tid >> 3;
                int n4 = (tid & 7) * 4;
                float4 bv = *(const float4*)&Kmat[(k0 + kk)*256 + n0 + n4];
                float2* dst = (float2*)&sh.g.B2[kk][n4*2];
                dst[0] = make_float2(bv.x, bv.x);
                dst[1] = make_float2(bv.y, bv.y);
                dst[2] = make_float2(bv.z, bv.z);
                dst[3] = make_float2(bv.w, bv.w);
            }
            __syncthreads();
#pragma unroll
            for (int kk = 0; kk < 32; ++kk) {
                longlong2 av = *(const longlong2*)&sh.g.A[kk][ty*4];
                longlong2 bv = *(const longlong2*)&sh.g.B2[kk][tx*4];
                acc2[0][0] = ffma2((u64t)av.x, (u64t)bv.x, acc2[0][0]);
                acc2[1][0] = ffma2((u64t)av.y, (u64t)bv.x, acc2[1][0]);
                acc2[0][1] = ffma2((u64t)av.x, (u64t)bv.y, acc2[0][1]);
                acc2[1][1] = ffma2((u64t)av.y, (u64t)bv.y, acc2[1][1]);
            }
            __syncthreads();
        }
        float bs0 = __ldg(&bias[n0 + tx*2]);
        float bs1 = __ldg(&bias[n0 + tx*2 + 1]);
#pragma unroll
        for (int mp = 0; mp < 2; ++mp) {
            float2 c0 = f2up(acc2[mp][0]);
            float2 c1 = f2up(acc2[mp][1]);
            int r0 = rowBase + ty*4 + 2*mp;
            if (r0 < BT) {
                d_xk[r0*ZZ + n0 + tx*2]     = c0.x + bs0;
                d_xk[r0*ZZ + n0 + tx*2 + 1] = c1.x + bs1;
            }
            if (r0 + 1 < BT) {
                d_xk[(r0+1)*ZZ + n0 + tx*2]     = c0.y + bs0;
                d_xk[(r0+1)*ZZ + n0 + tx*2 + 1] = c1.y + bs1;
            }
        }
    } else {
        // ---- XW: shared-staged, 8 p per block, f32x2 over k pairs ----
        int pbase = (bx - 104) * 8;
        // stage W1b rows 64..191 into sW[j*52+k]
        for (int idx = tid; idx < 128*NK; idx += 256) {
            int j = idx / NK, k = idx - j*NK;
            sh.w.W[j*52 + k] = __ldg(&W1[(64 + j)*NK + k]);
        }
        // stage 8 X rows (32 float4 each)
        {
            int pl = tid >> 5, quad = tid & 31;
            ((float4*)sh.w.Xr[pl])[quad] = *(const float4*)&X[(pbase + pl)*128 + quad*4];
        }
        __syncthreads();

        int pl = tid >> 5, lane = tid & 31;
        int p = pbase + pl;
        if (lane < 25) {
            int k2 = lane * 2;
            u64t acc = f2pk(__ldg(&b1[k2]), __ldg(&b1[k2+1]));
            const float* xr = sh.w.Xr[pl];
#pragma unroll 8
            for (int j = 0; j < 128; ++j) {
                float x = xr[j];
                acc = ffma2(f2pk(x, x), *(const u64t*)&sh.w.W[j*52 + k2], acc);
            }
            float2 r = f2up(acc);
            d_XW[p*NKP + padpos(k2)]     = r.x;
            d_XW[p*NKP + padpos(k2 + 1)] = r.y;
        } else if (lane < 31) {
            // zero the 6 pad positions: 25,26,27,53,54,55
            int off = (lane <= 27) ? lane : lane + 25;
            d_XW[p*NKP + off] = 0.f;
        }
    }
}

// ---------------------------------------------------------------------------
// k_lstm: one block per batch. Thread j owns column j of rec (f32x2 packed).
// Activations computed by ALL 256 threads (own z) — only tanh(c) on the
// 2-warp critical path. h history in shared; epilogue computes g = ht@W1a.
// ---------------------------------------------------------------------------
__global__ void __launch_bounds__(256) k_lstm(const float* __restrict__ rec,
                                              const float* __restrict__ W1) {
    int b = blockIdx.x;
    int j = threadIdx.x;
    __shared__ __align__(16) float h_hist[TT][UU];  // 25.6 KB
    __shared__ float a_sh[ZZ];

    u64t rc2[32];
#pragma unroll
    for (int m = 0; m < 32; ++m)
        rc2[m] = f2pk(rec[(2*m)*ZZ + j], rec[(2*m+1)*ZZ + j]);

    int grp = j >> 6;                 // 0:i 1:f 2:g 3:o
    float c = 0.f;
    float xk_next = d_xk[(b*TT)*ZZ + j];

#pragma unroll 1
    for (int t = 0; t < TT; ++t) {
        float xk = xk_next;
        if (t + 1 < TT) xk_next = d_xk[(b*TT + t + 1)*ZZ + j];
        float z;
        if (t == 0) {
            z = xk;
        } else {
            const longlong2* h8 = (const longlong2*)h_hist[t-1];
            u64t z0 = f2pk(xk, 0.f), z1 = 0ull, z2 = 0ull, z3 = 0ull;
#pragma unroll
            for (int i = 0; i < 8; ++i) {
                longlong2 hA = h8[i], hB = h8[i+8];
                z0 = ffma2((u64t)hA.x, rc2[2*i],    z0);
                z1 = ffma2((u64t)hA.y, rc2[2*i+1],  z1);
                z2 = ffma2((u64t)hB.x, rc2[2*i+16], z2);
                z3 = ffma2((u64t)hB.y, rc2[2*i+17], z3);
            }
            float2 r = f2up(fadd2(fadd2(z0, z1), fadd2(z2, z3)));
            z = r.x + r.y;
        }
        // activation in-thread (sigmoid for i,f,o; tanh for g)
        a_sh[j] = (grp == 2) ? tanhfast(z) : sigf(z);
        __syncthreads();
        if (j < UU) {
            float ai = a_sh[j], af = a_sh[64+j], ag = a_sh[128+j], ao = a_sh[192+j];
            c = fmaf(af, c, ai*ag);
            h_hist[t][j] = ao * tanhfast(c);
        }
        __syncthreads();
    }

    // epilogue: g[b,t,k] = sum_u h_hist[t][u] * W1[u*50+k]  (padded store)
    int k = j & 63, tc = j >> 6;
    if (k < NK) {
        u64t w1c[32];
#pragma unroll
        for (int m = 0; m < 32; ++m)
            w1c[m] = f2pk(__ldg(&W1[(2*m)*NK + k]), __ldg(&W1[(2*m+1)*NK + k]));
        int off = padpos(k);
#pragma unroll 1
        for (int tt = tc*25; tt < tc*25 + 25; ++tt) {
            const longlong2* h8 = (const longlong2*)h_hist[tt];
            u64t g0 = 0ull, g1 = 0ull, g2 = 0ull, g3 = 0ull;
#pragma unroll
            for (int i = 0; i < 8; ++i) {
                longlong2 hA = h8[i], hB = h8[i+8];
                g0 = ffma2((u64t)hA.x, w1c[2*i],    g0);
                g1 = ffma2((u64t)hA.y, w1c[2*i+1],  g1);
                g2 = ffma2((u64t)hB.x, w1c[2*i+16], g2);
                g3 = ffma2((u64t)hB.y, w1c[2*i+17], g3);
            }
            float2 r = f2up(fadd2(fadd2(g0, g1), fadd2(g2, g3)));
            d_g[(b*TT + tt)*NKP + off] = r.x + r.y;
        }
    } else if (k < 56) {
        int off = (k >= 53) ? k : (k - 25);
        for (int tt = tc*25; tt < tc*25 + 25; ++tt)
            d_g[(b*TT + tt)*NKP + off] = 0.f;
    }
}

// ---------------------------------------------------------------------------
// k_main: 128 threads = 32 p x 4 k-quarters (14 padded each). acc init = xw.
//   acc += a[b,t,p]*g[b,t,:]; pred = relu(acc)·W2 + b2 (suffix over t)
// grid (32, 8)
// ---------------------------------------------------------------------------
__global__ void __launch_bounds__(128) k_main(
    const int* __restrict__ pro_id, const float* __restrict__ cosX,
    const float* __restrict__ W2, const float* __restrict__ b2,
    float* __restrict__ out) {
    __shared__ __align__(16) float g_sh[TT*NKP];   // 22.4 KB
    __shared__ int pid_sh[TT];

    int b   = blockIdx.y;
    int tid = threadIdx.x;
    {
        const float4* gg = (const float4*)&d_g[b*TT*NKP];
        float4* gs = (float4*)g_sh;
        for (int i = tid; i < (TT*NKP)/4; i += 128) gs[i] = gg[i];
        for (int t = tid; t < TT; t += 128) pid_sh[t] = pro_id[b*TT + t];
    }
    __syncthreads();

    int p = blockIdx.x*32 + (tid >> 2);
    int q = tid & 3;
    bool valid = (p < PP);
    int pc = valid ? p : (PP - 1);

    float acc[14], w2r[14];
    {
        const float2* x2 = (const float2*)&d_XW[p*NKP + q*14];
#pragma unroll
        for (int m = 0; m < 7; ++m) { float2 v = x2[m]; acc[2*m] = v.x; acc[2*m+1] = v.y; }
    }
#pragma unroll
    for (int jj = 0; jj < 14; ++jj) {
        int pos = q*14 + jj;
        int k = (pos < 25) ? pos : ((pos >= 28 && pos < 53) ? pos - 3 : -1);
        w2r[jj] = (k >= 0) ? __ldg(&W2[k]) : 0.f;
    }
    float b2v = __ldg(b2);

    float av = __ldg(&cosX[pid_sh[TT-1]*PP + pc]);
#pragma unroll 1
    for (int t = TT - 1; t >= 0; --t) {
        float avn = (t > 0) ? __ldg(&cosX[pid_sh[t-1]*PP + pc]) : 0.f;
        const float2* g2 = (const float2*)&g_sh[t*NKP + q*14];
#pragma unroll
        for (int m = 0; m < 7; ++m) {
            float2 gv = g2[m];
            acc[2*m]   = fmaf(av, gv.x, acc[2*m]);
            acc[2*m+1] = fmaf(av, gv.y, acc[2*m+1]);
        }
        float d0 = 0.f, d1 = 0.f;
#pragma unroll
        for (int jj = 0; jj < 14; jj += 2) {
            d0 = fmaf(fmaxf(acc[jj],   0.f), w2r[jj],   d0);
            d1 = fmaf(fmaxf(acc[jj+1], 0.f), w2r[jj+1], d1);
        }
        float d = d0 + d1;
        d += __shfl_xor_sync(0xffffffffu, d, 1);
        d += __shfl_xor_sync(0xffffffffu, d, 2);
        if (q == 0 && valid) out[(b*TT + t)*PP + p] = d + b2v;
        av = avn;
    }
}

// ---------------------------------------------------------------------------
// Size-driven input resolution (robust to scalar presence / ordering).
// ---------------------------------------------------------------------------
extern "C" void kernel_launch(void* const* d_in, const int* in_sizes, int n_in,
                              void* d_out, int out_size) {
    const int *pro_id = 0, *label = 0;
    const float *X = 0, *cos_X = 0, *onehot = 0, *Kmat = 0, *rec = 0,
                *bias = 0, *W1 = 0, *b1 = 0, *W2 = 0, *b2 = 0;

    int n_ones = 0;
    for (int i = 0; i < n_in; ++i) if (in_sizes[i] == 1) n_ones++;
    int ones_seen = 0;

    for (int i = 0; i < n_in; ++i) {
        switch (in_sizes[i]) {
            case 800:     if (!pro_id) pro_id = (const int*)d_in[i];
                          else         label  = (const int*)d_in[i];      break;
            case 128000:  X      = (const float*)d_in[i];                 break;
            case 1000000: cos_X  = (const float*)d_in[i];                 break;
            case 10000:   /* trimatrix: tril(ones), hardcoded */          break;
            case 512:     onehot = (const float*)d_in[i];                 break;
            case 65536:   Kmat   = (const float*)d_in[i];                 break;
            case 16384:   rec    = (const float*)d_in[i];                 break;
            case 256:     bias   = (const float*)d_in[i];                 break;
            case 9600:    W1     = (const float*)d_in[i];                 break;
            case 50:      if (!b1) b1 = (const float*)d_in[i];
                          else     W2 = (const float*)d_in[i];            break;
            case 1:       ones_seen++;
                          if (ones_seen == n_ones) b2 = (const float*)d_in[i];
                          break;
            default: break;
        }
    }

    float* out = (float*)d_out;

    k_pre <<<229, 256>>>(pro_id, label, X, onehot, Kmat, bias, W1, b1);
    k_lstm<<<BB, 256>>>(rec, W1);
    k_main<<<dim3(32, BB), 128>>>(pro_id, cos_X, W2, b2, out);
}